// round 12
// baseline (speedup 1.0000x reference)
#include <cuda_runtime.h>
#include <cuda_bf16.h>
#include <math.h>

#define POOL 7
#define MAXS 15          // max box span (sizes<223px @ stride 16)
#define CHUNK 8          // float4s per channel chunk = 128 B per point

__device__ __forceinline__ float read_stride(const void* p) {
    int iv = *(const int*)p;
    if (iv >= 1 && iv <= 65536) return (float)iv;
    return *(const float*)p;
}

__device__ __forceinline__ float4 lerp4(float4 a, float4 b, float t) {
    float4 r;
    r.x = a.x + (b.x - a.x) * t;
    r.y = a.y + (b.y - a.y) * t;
    r.z = a.z + (b.z - a.z) * t;
    r.w = a.w + (b.w - a.w) * t;
    return r;
}

// One block per (channel-chunk, roi): grid (32, 512), 256 threads.
// Phase 1: stage the ROI's nr x nc box (128 B per point) into 28.8 KB static
//          smem — each distinct feature point leaves L2 exactly ONCE.
//          Mapping: 240 threads = 2 rows x 15 cols x 8 lanes, loop row-pairs,
//          no division, all loads independent (MLP ~= nr/2 per thread).
// Phase 2: 49 outputs = 4 LDS.128 + 3 lerps + 1 STG.128 each.
// 28.8 KB smem -> 7 blocks/SM (occ ~87%), fixing R6's occupancy collapse.
__global__ void __launch_bounds__(256)
roi_pool_kernel(const float* __restrict__ feat,
                const float* __restrict__ rois,
                const void* __restrict__ stride_p,
                float* __restrict__ out,
                int W, int C4) {
    __shared__ float4 box[MAXS * MAXS * CHUNK];           // 28.8 KB
    __shared__ int    s_y0[POOL], s_y1[POOL], s_x0[POOL], s_x1[POOL];
    __shared__ float  s_dy[POOL], s_dx[POOL];

    const int chunk = blockIdx.x;                         // 0..31
    const int n     = blockIdx.y;                         // roi
    const int tid   = threadIdx.x;

    // ---- uniform box coordinates ----
    const float s = read_stride(stride_p);
    const int ymin = (int)(rois[4 * n + 0] / s);
    const int xmin = (int)(rois[4 * n + 1] / s);
    const int ymax = (int)(rois[4 * n + 2] / s);
    const int xmax = (int)(rois[4 * n + 3] / s);
    int nr = ymax - ymin + 1; if (nr > MAXS) nr = MAXS;
    int nc = xmax - xmin + 1; if (nc > MAXS) nc = MAXS;

    // ---- sample tables (14 threads; ROI-relative indices, clamped to box) ----
    if (tid < POOL) {
        const float sy  = (float)nr / (float)POOL;
        const float src = (float)tid * sy;
        const int   i0  = (int)floorf(src);
        s_y0[tid] = i0;
        s_y1[tid] = min(i0 + 1, nr - 1);
        s_dy[tid] = src - (float)i0;
    } else if (tid >= 8 && tid < 8 + POOL) {
        const int   px  = tid - 8;
        const float sx  = (float)nc / (float)POOL;
        const float src = (float)px * sx;
        const int   i0  = (int)floorf(src);
        s_x0[px] = i0;
        s_x1[px] = min(i0 + 1, nc - 1);
        s_dx[px] = src - (float)i0;
    }

    // ---- phase 1: stage box (no division, independent loads) ----
    // 240 active threads = 2 rows x 15 cols x 8 lanes
    const int  rr    = (tid >= 120) ? 1 : 0;
    const int  base  = tid - rr * 120;
    const int  col   = base >> 3;          // 0..14
    const int  lane  = base & 7;           // 0..7
    const bool active = (tid < 240) && (col < nc);

    const float4* __restrict__ f4  = (const float4*)feat;
    const float4* __restrict__ src = f4 + (ymin * W + xmin) * C4 + chunk * CHUNK + lane;

    if (active) {
#pragma unroll 4
        for (int r = rr; r < nr; r += 2) {
            box[(r * nc + col) * CHUNK + lane] = src[(r * W + col) * C4];
        }
    }
    __syncthreads();

    // ---- phase 2: 49 outputs from smem ----
    const int g  = tid >> 3;               // output group 0..31
    const int ln = tid & 7;                // float4 lane within 128 B chunk
    float4* __restrict__ o = (float4*)out + n * (POOL * POOL) * C4 + chunk * CHUNK + ln;

#pragma unroll
    for (int it = 0; it < 2; ++it) {
        const int oidx = it * 32 + g;
        if (oidx < POOL * POOL) {
            const int py = oidx / POOL;            // /7 -> magic-number mul
            const int px = oidx - py * POOL;
            const int r0 = s_y0[py], r1 = s_y1[py];
            const int c0 = s_x0[px], c1 = s_x1[px];
            const float dy = s_dy[py], dx = s_dx[px];

            const float4 f00 = box[(r0 * nc + c0) * CHUNK + ln];
            const float4 f01 = box[(r0 * nc + c1) * CHUNK + ln];
            const float4 f10 = box[(r1 * nc + c0) * CHUNK + ln];
            const float4 f11 = box[(r1 * nc + c1) * CHUNK + ln];

            const float4 top = lerp4(f00, f01, dx);   // reference op order
            const float4 bot = lerp4(f10, f11, dx);
            o[oidx * C4] = lerp4(top, bot, dy);
        }
    }
}

extern "C" void kernel_launch(void* const* d_in, const int* in_sizes, int n_in,
                              void* d_out, int out_size) {
    const float* feat  = (const float*)d_in[0];   // (1, H, W, C) fp32
    const float* rois  = (const float*)d_in[1];   // (N, 4) fp32
    const void*  strid = d_in[2];                 // scalar

    int N = in_sizes[1] / 4;
    int C = out_size / (N * POOL * POOL);         // 1024
    int HW = in_sizes[0] / C;                     // 4096
    int W = 1;
    while (W * W < HW) W <<= 1;                   // 64
    if (W * W != HW) {
        W = (int)(sqrtf((float)HW) + 0.5f);
    }
    int C4 = C / 4;                               // 256

    dim3 grid(C4 / CHUNK, N);                     // (32, 512)
    roi_pool_kernel<<<grid, 256>>>(feat, rois, strid, (float*)d_out, W, C4);
}

// round 13
// speedup vs baseline: 1.5942x; 1.5942x over previous
#include <cuda_runtime.h>
#include <cuda_bf16.h>
#include <math.h>

#define POOL 7

__device__ __forceinline__ float read_stride(const void* p) {
    int iv = *(const int*)p;
    if (iv >= 1 && iv <= 65536) return (float)iv;
    return *(const float*)p;
}

__device__ __forceinline__ float4 lerp4(float4 a, float4 b, float t) {
    float4 r;
    r.x = a.x + (b.x - a.x) * t;
    r.y = a.y + (b.y - a.y) * t;
    r.z = a.z + (b.z - a.z) * t;
    r.w = a.w + (b.w - a.w) * t;
    return r;
}

// grid (2, N): blockIdx.x = channel half. 256 threads = 128 channel lanes x
// 2 py-groups (warps 0-3: py 0..3, warps 4-7: py 4..6). Branch-free direct
// 4-tap loads per px (R9 skeleton: high MLP, low regs, no selects). All
// redundancy — x-overlap (x1[px]==x0[px+1]) AND cross-py row reuse within a
// group — is same-address loads resolved in L1 (reuse distance ~ one py
// iteration), so L2 sees mostly distinct box points. 1024 blocks x 8 warps =
// 8192 warps keeps the LTS fed.
__global__ void __launch_bounds__(256)
roi_pool_kernel(const float* __restrict__ feat,
                const float* __restrict__ rois,
                const void* __restrict__ stride_p,
                float* __restrict__ out,
                int W, int C4) {
    const int half = blockIdx.x;                  // 0..1
    const int n    = blockIdx.y;                  // roi
    const int tid  = threadIdx.x;
    const int lane = tid & 127;                   // channel float4 lane
    const int g    = tid >> 7;                    // py-group 0/1
    const int c    = half * 128 + lane;

    // ---- uniform coordinate math ----
    const float s = read_stride(stride_p);
    const int ymin = (int)(rois[4 * n + 0] / s);
    const int xmin = (int)(rois[4 * n + 1] / s);
    const int ymax = (int)(rois[4 * n + 2] / s);
    const int xmax = (int)(rois[4 * n + 3] / s);

    const int   spany = ymax - ymin;
    const float sy    = (float)(spany + 1) / (float)POOL;
    const int   spanx = xmax - xmin;
    const float sx    = (float)(spanx + 1) / (float)POOL;

    int   ox0[POOL], ox1[POOL];
    float dxv[POOL];
#pragma unroll
    for (int px = 0; px < POOL; ++px) {
        const float srcx = (float)px * sx;
        const int   ix0  = (int)floorf(srcx);
        dxv[px] = srcx - (float)ix0;
        ox0[px] = (xmin + ix0) * C4;
        ox1[px] = (xmin + min(ix0 + 1, spanx)) * C4;
    }

    const float4* __restrict__ f = (const float4*)feat;
    float4* __restrict__ o = (float4*)out + n * (POOL * POOL) * C4 + c;

    const int py_lo = g ? 4 : 0;
    const int py_hi = g ? POOL : 4;

    for (int py = py_lo; py < py_hi; ++py) {
        const float srcy = (float)py * sy;
        const int   iy0  = (int)floorf(srcy);
        const float dy   = srcy - (float)iy0;
        const int   y0   = ymin + iy0;
        const int   y1   = ymin + min(iy0 + 1, spany);

        const float4* __restrict__ r0 = f + y0 * W * C4 + c;
        const float4* __restrict__ r1 = f + y1 * W * C4 + c;

#pragma unroll
        for (int px = 0; px < POOL; ++px) {
            const int   o0 = ox0[px];
            const int   o1 = ox1[px];
            const float dx = dxv[px];

            const float4 f00 = r0[o0];    // duplicates across px/py -> L1 hits
            const float4 f01 = r0[o1];
            const float4 f10 = r1[o0];
            const float4 f11 = r1[o1];

            const float4 top = lerp4(f00, f01, dx);   // reference op order
            const float4 bot = lerp4(f10, f11, dx);
            o[(py * POOL + px) * C4] = lerp4(top, bot, dy);
        }
    }
}

extern "C" void kernel_launch(void* const* d_in, const int* in_sizes, int n_in,
                              void* d_out, int out_size) {
    const float* feat  = (const float*)d_in[0];   // (1, H, W, C) fp32
    const float* rois  = (const float*)d_in[1];   // (N, 4) fp32
    const void*  strid = d_in[2];                 // scalar

    int N = in_sizes[1] / 4;
    int C = out_size / (N * POOL * POOL);         // 1024
    int HW = in_sizes[0] / C;                     // 4096
    int W = 1;
    while (W * W < HW) W <<= 1;                   // 64
    if (W * W != HW) {
        W = (int)(sqrtf((float)HW) + 0.5f);
    }
    int C4 = C / 4;                               // 256

    dim3 grid(2, N);                              // (2, 512)
    roi_pool_kernel<<<grid, 256>>>(feat, rois, strid, (float*)d_out, W, C4);
}